// round 4
// baseline (speedup 1.0000x reference)
#include <cuda_runtime.h>
#include <cstdint>
#include <cstring>

#define BB 16
#define NN 128
#define DD 128

// Scratch (device globals — allocations forbidden)
__device__ float g_xfull[BB * NN * 512];   // [hhat | deg*h | ehat | h]  (4 MB)
__device__ float g_G[512 * 128];           // fused weight (256 KB)
__device__ float g_bb[128];                // bm @ Wu2^T
__device__ float g_deg[BB * NN];

// ---------------------------------------------------------------------------
// prep: G[c,k] = sum_q Wm[q,c] * Wu[k,128+q]  (c<384);  G[384+d,k] = Wu[k,d]
//       bb[k]  = sum_q bm[q]   * Wu[k,128+q]
// grid 128 (one block per k), 128 threads.
// ---------------------------------------------------------------------------
__global__ void __launch_bounds__(128) prep_kernel(
    const float* __restrict__ Wm, const float* __restrict__ Wu,
    const float* __restrict__ bm, float* __restrict__ G, float* __restrict__ bb)
{
    const int k = blockIdx.x;
    const int tid = threadIdx.x;
    __shared__ float s_wu[128];
    s_wu[tid] = Wu[(size_t)k * 256 + 128 + tid];
    __syncthreads();

    float a0 = 0.f, a1 = 0.f, a2 = 0.f;
    #pragma unroll 4
    for (int q = 0; q < 128; ++q) {
        const float wq = s_wu[q];
        const float* wr = Wm + (size_t)q * 384;
        a0 += wr[tid]       * wq;
        a1 += wr[tid + 128] * wq;
        a2 += wr[tid + 256] * wq;
    }
    G[(size_t)tid * 128 + k]         = a0;
    G[(size_t)(tid + 128) * 128 + k] = a1;
    G[(size_t)(tid + 256) * 128 + k] = a2;
    G[(size_t)(tid + 384) * 128 + k] = Wu[(size_t)k * 256 + tid];

    if (tid < 32) {
        float s = 0.f;
        for (int q = tid; q < 128; q += 32) s += bm[q] * s_wu[q];
        #pragma unroll
        for (int off = 16; off; off >>= 1) s += __shfl_down_sync(0xffffffffu, s, off);
        if (tid == 0) bb[k] = s;
    }
}

// ---------------------------------------------------------------------------
// reduce: per (b,j) block, 256 threads (8 warps).
//   ehat[d] = sum_i adj[b,i,j]*e[b,i,j,d],  hhat[d] = sum_i adj*h[b,i,d]
// Ballot-compacted nonzero i-list; warp-strided float4 main loop; smem tree.
// Writes xfull row = [hhat | deg*h | ehat | h], deg.
// ---------------------------------------------------------------------------
__global__ void __launch_bounds__(256) reduce_kernel(
    const float* __restrict__ h,
    const float* __restrict__ adj,
    const float* __restrict__ e,
    float* __restrict__ xfull,
    float* __restrict__ deg_out)
{
    const int j = blockIdx.x;
    const int b = blockIdx.y;
    const int tid  = threadIdx.x;
    const int lane = tid & 31;
    const int w    = tid >> 5;

    // float4-accessed arrays MUST be 16B-aligned (shared float arrays default
    // to 4B alignment; the R3 fault was a misaligned float4 store into s_re).
    __shared__ __align__(16) float s_re[8][DD];
    __shared__ __align__(16) float s_rh[8][DD];
    __shared__ float    s_val[NN];
    __shared__ int      s_idx[NN];
    __shared__ unsigned s_ball[4];
    __shared__ float    s_wsum[4];
    __shared__ int      s_cnt;
    __shared__ float    s_deg;

    float a = 0.f;
    if (tid < NN) {
        a = adj[((size_t)b * NN + tid) * NN + j];
        unsigned ball = __ballot_sync(0xffffffffu, a != 0.f);
        float s = a;
        #pragma unroll
        for (int off = 16; off; off >>= 1) s += __shfl_down_sync(0xffffffffu, s, off);
        if (lane == 0) { s_ball[w] = ball; s_wsum[w] = s; }
    }
    __syncthreads();
    if (tid < NN) {
        int base = 0;
        #pragma unroll
        for (int ww = 0; ww < 4; ++ww) if (ww < w) base += __popc(s_ball[ww]);
        const unsigned ball = s_ball[w];
        if (a != 0.f) {
            const int pos = base + __popc(ball & ((1u << lane) - 1u));
            s_idx[pos] = tid;
            s_val[pos] = a;
        }
        if (tid == 0) {
            s_cnt = __popc(s_ball[0]) + __popc(s_ball[1]) + __popc(s_ball[2]) + __popc(s_ball[3]);
            s_deg = s_wsum[0] + s_wsum[1] + s_wsum[2] + s_wsum[3];
        }
    }
    __syncthreads();

    const int   cnt = s_cnt;
    const float deg = s_deg;

    // e[b,i,j,d] base (i=0): (b*NN*NN + j)*DD ; stride over i: NN*DD
    const float* __restrict__ eb = e + ((size_t)b * NN * NN + (size_t)j) * DD + lane * 4;
    const float* __restrict__ hb = h + (size_t)b * NN * DD + lane * 4;

    float4 ae = make_float4(0.f, 0.f, 0.f, 0.f);
    float4 ah = make_float4(0.f, 0.f, 0.f, 0.f);
    #pragma unroll 4
    for (int t = w; t < cnt; t += 8) {
        const float aa = s_val[t];
        const int   i  = s_idx[t];
        const float4 ev = *(const float4*)(eb + (size_t)i * (NN * DD));
        const float4 hv = *(const float4*)(hb + (size_t)i * DD);
        ae.x += aa * ev.x; ae.y += aa * ev.y; ae.z += aa * ev.z; ae.w += aa * ev.w;
        ah.x += aa * hv.x; ah.y += aa * hv.y; ah.z += aa * hv.z; ah.w += aa * hv.w;
    }
    *(float4*)&s_re[w][lane * 4] = ae;
    *(float4*)&s_rh[w][lane * 4] = ah;
    __syncthreads();

    if (tid < NN) {
        float se = 0.f, sh = 0.f;
        #pragma unroll
        for (int ww = 0; ww < 8; ++ww) { se += s_re[ww][tid]; sh += s_rh[ww][tid]; }
        const size_t r  = (size_t)b * NN + j;
        const float  hv = h[r * DD + tid];
        xfull[r * 512 + tid]       = sh;        // hhat
        xfull[r * 512 + 128 + tid] = deg * hv;  // deg*h
        xfull[r * 512 + 256 + tid] = se;        // ehat
        xfull[r * 512 + 384 + tid] = hv;        // h
        if (tid == 0) deg_out[r] = deg;
    }
}

// ---------------------------------------------------------------------------
// Final GEMM: C(2048x128) = A(2048x512) @ G(512x128) + deg⊗bb + bu
// BM=32, BN=64, BK=16, 256 threads, TM=2, TN=4, packed f32x2 FMAs.
// grid (128/64, 2048/32) = (2, 64) = 128 blocks.
// ---------------------------------------------------------------------------
#define GBM 32
#define GBN 64
#define GBK 16

__device__ __forceinline__ unsigned long long f2ull(float2 v) {
    unsigned long long u; memcpy(&u, &v, 8); return u;
}
__device__ __forceinline__ float2 ull2f(unsigned long long u) {
    float2 v; memcpy(&v, &u, 8); return v;
}

__global__ void __launch_bounds__(256) gemm_final(
    const float* __restrict__ A,
    const float* __restrict__ G,
    const float* __restrict__ bb,
    const float* __restrict__ bu,
    const float* __restrict__ deg,
    float* __restrict__ C)
{
    __shared__ __align__(16) float2 As2[GBK][GBM + 1];  // duplicated {v,v}
    __shared__ __align__(16) float  Bs[GBK][GBN];

    const int m0 = blockIdx.y * GBM;
    const int n0 = blockIdx.x * GBN;
    const int tid = threadIdx.x;
    const int tx = tid & 15;    // n-group (4 cols)
    const int ty = tid >> 4;    // m-group (2 rows)

    const int am = tid >> 3;          // 0..31
    const int ak = (tid & 7) * 2;     // 0..14
    const int bk = tid >> 4;          // 0..15
    const int bc = (tid & 15) * 4;    // 0..60

    unsigned long long acc[2][2];
    acc[0][0] = acc[0][1] = acc[1][0] = acc[1][1] = 0ull;

    for (int k0 = 0; k0 < 512; k0 += GBK) {
        const float2 av = *(const float2*)(A + (size_t)(m0 + am) * 512 + k0 + ak);
        As2[ak][am]     = make_float2(av.x, av.x);
        As2[ak + 1][am] = make_float2(av.y, av.y);
        *(float4*)&Bs[bk][bc] = *(const float4*)(G + (size_t)(k0 + bk) * 128 + n0 + bc);
        __syncthreads();

        #pragma unroll
        for (int kk = 0; kk < GBK; ++kk) {
            const unsigned long long rm0 = f2ull(As2[kk][ty * 2 + 0]);
            const unsigned long long rm1 = f2ull(As2[kk][ty * 2 + 1]);
            const float4 rn = *(const float4*)&Bs[kk][tx * 4];
            const unsigned long long rnA = f2ull(make_float2(rn.x, rn.y));
            const unsigned long long rnB = f2ull(make_float2(rn.z, rn.w));
            asm("fma.rn.f32x2 %0, %1, %2, %0;" : "+l"(acc[0][0]) : "l"(rm0), "l"(rnA));
            asm("fma.rn.f32x2 %0, %1, %2, %0;" : "+l"(acc[0][1]) : "l"(rm0), "l"(rnB));
            asm("fma.rn.f32x2 %0, %1, %2, %0;" : "+l"(acc[1][0]) : "l"(rm1), "l"(rnA));
            asm("fma.rn.f32x2 %0, %1, %2, %0;" : "+l"(acc[1][1]) : "l"(rm1), "l"(rnB));
        }
        __syncthreads();
    }

    #pragma unroll
    for (int q = 0; q < 2; ++q) {
        const int row = m0 + ty * 2 + q;
        const float dg = deg[row];
        #pragma unroll
        for (int p = 0; p < 2; ++p) {
            const float2 v = ull2f(acc[q][p]);
            const int c0 = n0 + tx * 4 + p * 2;
            C[(size_t)row * 128 + c0]     = v.x + dg * bb[c0]     + bu[c0];
            C[(size_t)row * 128 + c0 + 1] = v.y + dg * bb[c0 + 1] + bu[c0 + 1];
        }
    }
}

// ---------------------------------------------------------------------------
// kernel_launch: inputs: h, adj, e, Wm, bm, Wu, bu ; output (B,N,D) fp32
// ---------------------------------------------------------------------------
extern "C" void kernel_launch(void* const* d_in, const int* in_sizes, int n_in,
                              void* d_out, int out_size)
{
    const float* h   = (const float*)d_in[0];
    const float* adj = (const float*)d_in[1];
    const float* e   = (const float*)d_in[2];
    const float* Wm  = (const float*)d_in[3];
    const float* bm  = (const float*)d_in[4];
    const float* Wu  = (const float*)d_in[5];
    const float* bu  = (const float*)d_in[6];
    float* out = (float*)d_out;

    float* xfull; cudaGetSymbolAddress((void**)&xfull, g_xfull);
    float* G;     cudaGetSymbolAddress((void**)&G,     g_G);
    float* bb;    cudaGetSymbolAddress((void**)&bb,    g_bb);
    float* deg;   cudaGetSymbolAddress((void**)&deg,   g_deg);

    prep_kernel<<<128, 128>>>(Wm, Wu, bm, G, bb);

    {
        dim3 grid(NN, BB);
        reduce_kernel<<<grid, 256>>>(h, adj, e, xfull, deg);
    }
    {
        dim3 grid(128 / GBN, (BB * NN) / GBM);   // (2, 64)
        gemm_final<<<grid, 256>>>(xfull, G, bb, bu, deg, out);
    }
}

// round 5
// speedup vs baseline: 1.0052x; 1.0052x over previous
#include <cuda_runtime.h>
#include <cstdint>
#include <cstring>

#define BB 16
#define NN 128
#define DD 128

// Scratch (device globals — allocations forbidden)
__device__ float g_xfull[BB * NN * 512];   // [hhat | deg*h | ehat | h]  (4 MB)
__device__ float g_G[512 * 128];           // fused weight (256 KB)
__device__ float g_bb[128];                // bm @ Wu2^T
__device__ float g_deg[BB * NN];

// ---------------------------------------------------------------------------
// prep: G[c,k] = sum_q Wm[q,c] * Wu[k,128+q]  (c<384);  G[384+d,k] = Wu[k,d]
//       bb[k]  = sum_q bm[q]   * Wu[k,128+q]
// grid 128 (one block per k), 128 threads.
// ---------------------------------------------------------------------------
__global__ void __launch_bounds__(128) prep_kernel(
    const float* __restrict__ Wm, const float* __restrict__ Wu,
    const float* __restrict__ bm, float* __restrict__ G, float* __restrict__ bb)
{
    const int k = blockIdx.x;
    const int tid = threadIdx.x;
    __shared__ float s_wu[128];
    s_wu[tid] = Wu[(size_t)k * 256 + 128 + tid];
    __syncthreads();

    float a0 = 0.f, a1 = 0.f, a2 = 0.f;
    #pragma unroll 4
    for (int q = 0; q < 128; ++q) {
        const float wq = s_wu[q];
        const float* wr = Wm + (size_t)q * 384;
        a0 += wr[tid]       * wq;
        a1 += wr[tid + 128] * wq;
        a2 += wr[tid + 256] * wq;
    }
    G[(size_t)tid * 128 + k]         = a0;
    G[(size_t)(tid + 128) * 128 + k] = a1;
    G[(size_t)(tid + 256) * 128 + k] = a2;
    G[(size_t)(tid + 384) * 128 + k] = Wu[(size_t)k * 256 + tid];

    if (tid < 32) {
        float s = 0.f;
        for (int q = tid; q < 128; q += 32) s += bm[q] * s_wu[q];
        #pragma unroll
        for (int off = 16; off; off >>= 1) s += __shfl_down_sync(0xffffffffu, s, off);
        if (tid == 0) bb[k] = s;
    }
}

// ---------------------------------------------------------------------------
// reduce: per (b,j) block, 256 threads (8 warps).
//   ehat[d] = sum_i adj[b,i,j]*e[b,i,j,d],  hhat[d] = sum_i adj*h[b,i,d]
// Ballot-compacted nonzero i-list; warp-strided float4 main loop; smem tree.
// Writes xfull row = [hhat | deg*h | ehat | h], deg.
// ---------------------------------------------------------------------------
__global__ void __launch_bounds__(256) reduce_kernel(
    const float* __restrict__ h,
    const float* __restrict__ adj,
    const float* __restrict__ e,
    float* __restrict__ xfull,
    float* __restrict__ deg_out)
{
    const int j = blockIdx.x;
    const int b = blockIdx.y;
    const int tid  = threadIdx.x;
    const int lane = tid & 31;
    const int w    = tid >> 5;

    // float4-accessed arrays MUST be 16B-aligned (shared float arrays default
    // to 4B alignment; the R3 fault was a misaligned float4 store into s_re).
    __shared__ __align__(16) float s_re[8][DD];
    __shared__ __align__(16) float s_rh[8][DD];
    __shared__ float    s_val[NN];
    __shared__ int      s_idx[NN];
    __shared__ unsigned s_ball[4];
    __shared__ float    s_wsum[4];
    __shared__ int      s_cnt;
    __shared__ float    s_deg;

    float a = 0.f;
    if (tid < NN) {
        a = adj[((size_t)b * NN + tid) * NN + j];
        unsigned ball = __ballot_sync(0xffffffffu, a != 0.f);
        float s = a;
        #pragma unroll
        for (int off = 16; off; off >>= 1) s += __shfl_down_sync(0xffffffffu, s, off);
        if (lane == 0) { s_ball[w] = ball; s_wsum[w] = s; }
    }
    __syncthreads();
    if (tid < NN) {
        int base = 0;
        #pragma unroll
        for (int ww = 0; ww < 4; ++ww) if (ww < w) base += __popc(s_ball[ww]);
        const unsigned ball = s_ball[w];
        if (a != 0.f) {
            const int pos = base + __popc(ball & ((1u << lane) - 1u));
            s_idx[pos] = tid;
            s_val[pos] = a;
        }
        if (tid == 0) {
            s_cnt = __popc(s_ball[0]) + __popc(s_ball[1]) + __popc(s_ball[2]) + __popc(s_ball[3]);
            s_deg = s_wsum[0] + s_wsum[1] + s_wsum[2] + s_wsum[3];
        }
    }
    __syncthreads();

    const int   cnt = s_cnt;
    const float deg = s_deg;

    // e[b,i,j,d] base (i=0): (b*NN*NN + j)*DD ; stride over i: NN*DD
    const float* __restrict__ eb = e + ((size_t)b * NN * NN + (size_t)j) * DD + lane * 4;
    const float* __restrict__ hb = h + (size_t)b * NN * DD + lane * 4;

    float4 ae = make_float4(0.f, 0.f, 0.f, 0.f);
    float4 ah = make_float4(0.f, 0.f, 0.f, 0.f);
    #pragma unroll 4
    for (int t = w; t < cnt; t += 8) {
        const float aa = s_val[t];
        const int   i  = s_idx[t];
        const float4 ev = *(const float4*)(eb + (size_t)i * (NN * DD));
        const float4 hv = *(const float4*)(hb + (size_t)i * DD);
        ae.x += aa * ev.x; ae.y += aa * ev.y; ae.z += aa * ev.z; ae.w += aa * ev.w;
        ah.x += aa * hv.x; ah.y += aa * hv.y; ah.z += aa * hv.z; ah.w += aa * hv.w;
    }
    *(float4*)&s_re[w][lane * 4] = ae;
    *(float4*)&s_rh[w][lane * 4] = ah;
    __syncthreads();

    if (tid < NN) {
        float se = 0.f, sh = 0.f;
        #pragma unroll
        for (int ww = 0; ww < 8; ++ww) { se += s_re[ww][tid]; sh += s_rh[ww][tid]; }
        const size_t r  = (size_t)b * NN + j;
        const float  hv = h[r * DD + tid];
        xfull[r * 512 + tid]       = sh;        // hhat
        xfull[r * 512 + 128 + tid] = deg * hv;  // deg*h
        xfull[r * 512 + 256 + tid] = se;        // ehat
        xfull[r * 512 + 384 + tid] = hv;        // h
        if (tid == 0) deg_out[r] = deg;
    }
}

// ---------------------------------------------------------------------------
// Final GEMM: C(2048x128) = A(2048x512) @ G(512x128) + deg⊗bb + bu
// BM=32, BN=64, BK=16, 256 threads, TM=2, TN=4, packed f32x2 FMAs.
// grid (128/64, 2048/32) = (2, 64) = 128 blocks.
// ---------------------------------------------------------------------------
#define GBM 32
#define GBN 64
#define GBK 16

__device__ __forceinline__ unsigned long long f2ull(float2 v) {
    unsigned long long u; memcpy(&u, &v, 8); return u;
}
__device__ __forceinline__ float2 ull2f(unsigned long long u) {
    float2 v; memcpy(&v, &u, 8); return v;
}

__global__ void __launch_bounds__(256) gemm_final(
    const float* __restrict__ A,
    const float* __restrict__ G,
    const float* __restrict__ bb,
    const float* __restrict__ bu,
    const float* __restrict__ deg,
    float* __restrict__ C)
{
    __shared__ __align__(16) float2 As2[GBK][GBM + 1];  // duplicated {v,v}
    __shared__ __align__(16) float  Bs[GBK][GBN];

    const int m0 = blockIdx.y * GBM;
    const int n0 = blockIdx.x * GBN;
    const int tid = threadIdx.x;
    const int tx = tid & 15;    // n-group (4 cols)
    const int ty = tid >> 4;    // m-group (2 rows)

    const int am = tid >> 3;          // 0..31
    const int ak = (tid & 7) * 2;     // 0..14
    const int bk = tid >> 4;          // 0..15
    const int bc = (tid & 15) * 4;    // 0..60

    unsigned long long acc[2][2];
    acc[0][0] = acc[0][1] = acc[1][0] = acc[1][1] = 0ull;

    for (int k0 = 0; k0 < 512; k0 += GBK) {
        const float2 av = *(const float2*)(A + (size_t)(m0 + am) * 512 + k0 + ak);
        As2[ak][am]     = make_float2(av.x, av.x);
        As2[ak + 1][am] = make_float2(av.y, av.y);
        *(float4*)&Bs[bk][bc] = *(const float4*)(G + (size_t)(k0 + bk) * 128 + n0 + bc);
        __syncthreads();

        #pragma unroll
        for (int kk = 0; kk < GBK; ++kk) {
            const unsigned long long rm0 = f2ull(As2[kk][ty * 2 + 0]);
            const unsigned long long rm1 = f2ull(As2[kk][ty * 2 + 1]);
            const float4 rn = *(const float4*)&Bs[kk][tx * 4];
            const unsigned long long rnA = f2ull(make_float2(rn.x, rn.y));
            const unsigned long long rnB = f2ull(make_float2(rn.z, rn.w));
            asm("fma.rn.f32x2 %0, %1, %2, %0;" : "+l"(acc[0][0]) : "l"(rm0), "l"(rnA));
            asm("fma.rn.f32x2 %0, %1, %2, %0;" : "+l"(acc[0][1]) : "l"(rm0), "l"(rnB));
            asm("fma.rn.f32x2 %0, %1, %2, %0;" : "+l"(acc[1][0]) : "l"(rm1), "l"(rnA));
            asm("fma.rn.f32x2 %0, %1, %2, %0;" : "+l"(acc[1][1]) : "l"(rm1), "l"(rnB));
        }
        __syncthreads();
    }

    #pragma unroll
    for (int q = 0; q < 2; ++q) {
        const int row = m0 + ty * 2 + q;
        const float dg = deg[row];
        #pragma unroll
        for (int p = 0; p < 2; ++p) {
            const float2 v = ull2f(acc[q][p]);
            const int c0 = n0 + tx * 4 + p * 2;
            C[(size_t)row * 128 + c0]     = v.x + dg * bb[c0]     + bu[c0];
            C[(size_t)row * 128 + c0 + 1] = v.y + dg * bb[c0 + 1] + bu[c0 + 1];
        }
    }
}

// ---------------------------------------------------------------------------
// kernel_launch: inputs: h, adj, e, Wm, bm, Wu, bu ; output (B,N,D) fp32
// ---------------------------------------------------------------------------
extern "C" void kernel_launch(void* const* d_in, const int* in_sizes, int n_in,
                              void* d_out, int out_size)
{
    const float* h   = (const float*)d_in[0];
    const float* adj = (const float*)d_in[1];
    const float* e   = (const float*)d_in[2];
    const float* Wm  = (const float*)d_in[3];
    const float* bm  = (const float*)d_in[4];
    const float* Wu  = (const float*)d_in[5];
    const float* bu  = (const float*)d_in[6];
    float* out = (float*)d_out;

    float* xfull; cudaGetSymbolAddress((void**)&xfull, g_xfull);
    float* G;     cudaGetSymbolAddress((void**)&G,     g_G);
    float* bb;    cudaGetSymbolAddress((void**)&bb,    g_bb);
    float* deg;   cudaGetSymbolAddress((void**)&deg,   g_deg);

    prep_kernel<<<128, 128>>>(Wm, Wu, bm, G, bb);

    {
        dim3 grid(NN, BB);
        reduce_kernel<<<grid, 256>>>(h, adj, e, xfull, deg);
    }
    {
        dim3 grid(128 / GBN, (BB * NN) / GBM);   // (2, 64)
        gemm_final<<<grid, 256>>>(xfull, G, bb, bu, deg, out);
    }
}

// round 6
// speedup vs baseline: 1.2124x; 1.2061x over previous
#include <cuda_runtime.h>
#include <cstdint>
#include <cstring>

#define BB 16
#define NN 128
#define DD 128

#define PREP_BLOCKS 256   // blocks 0..255 of fused kernel do weight-fusion prep

// Scratch (device globals — allocations forbidden)
__device__ float g_xfull[BB * NN * 512];   // [hhat | deg*h | ehat | h]  (4 MB)
__device__ float g_G[512 * 128];           // fused weight (256 KB)
__device__ float g_bb[128];                // bm @ Wu2^T
__device__ float g_deg[BB * NN];

// ---------------------------------------------------------------------------
// Fused kernel: grid = PREP_BLOCKS + B*N blocks, 256 threads.
//
// blocks [0, 256):   prep.  G[c,k] = sum_q Wm[q,c]*Wu[k,128+q] (c<384),
//                    G[384+d,k] = Wu[k,d];  bb[k] = sum_q bm[q]*Wu[k,128+q].
//                    2 c-rows per block, thread = (cl,k). Runs concurrently
//                    with (and hidden under) the reduce blocks' DRAM stream.
//
// blocks [256, 2304): reduce over i for one (b,j):
//                    ehat[d] = sum_i adj[b,i,j]*e[b,i,j,d]
//                    hhat[d] = sum_i adj[b,i,j]*h[b,i,d],  deg = sum_i adj
//                    Ballot-compacted i-list, warp-strided float4 main loop.
//                    Writes xfull row = [hhat | deg*h | ehat | h], deg.
// ---------------------------------------------------------------------------
__global__ void __launch_bounds__(256) fused_prep_reduce(
    const float* __restrict__ h,
    const float* __restrict__ adj,
    const float* __restrict__ e,
    const float* __restrict__ Wm,
    const float* __restrict__ Wu,
    const float* __restrict__ bm,
    float* __restrict__ xfull,
    float* __restrict__ deg_out,
    float* __restrict__ G,
    float* __restrict__ bb)
{
    const int tid  = threadIdx.x;
    const int lane = tid & 31;
    const int w    = tid >> 5;

    if (blockIdx.x < PREP_BLOCKS) {
        // ----------------------- prep path -----------------------
        __shared__ float s_wm[2][128];
        const int pid = blockIdx.x;
        const int c0  = pid * 2;
        const int cl  = tid >> 7;       // 0,1
        const int k   = tid & 127;

        // stage Wm columns c0, c0+1 (only meaningful for c < 384)
        {
            const int q   = tid & 127;
            const int cc  = c0 + (tid >> 7);
            s_wm[tid >> 7][q] = (cc < 384) ? Wm[(size_t)q * 384 + cc] : 0.f;
        }
        __syncthreads();

        const int c = c0 + cl;
        if (c < 384) {
            const float* __restrict__ wu = Wu + (size_t)k * 256 + 128;
            float acc = 0.f;
            #pragma unroll 4
            for (int q = 0; q < 128; q += 4) {
                const float4 v = *(const float4*)(wu + q);
                acc += s_wm[cl][q]     * v.x;
                acc += s_wm[cl][q + 1] * v.y;
                acc += s_wm[cl][q + 2] * v.z;
                acc += s_wm[cl][q + 3] * v.w;
            }
            G[(size_t)c * 128 + k] = acc;
        } else {
            G[(size_t)c * 128 + k] = Wu[(size_t)k * 256 + (c - 384)];
        }

        // bb computed once by block 0 (threads 0..127)
        if (pid == 0 && tid < 128) {
            const float* __restrict__ wu = Wu + (size_t)tid * 256 + 128;
            float acc = 0.f;
            #pragma unroll 4
            for (int q = 0; q < 128; q += 4) {
                const float4 v  = *(const float4*)(wu + q);
                const float4 bv = *(const float4*)(bm + q);
                acc += bv.x * v.x + bv.y * v.y + bv.z * v.z + bv.w * v.w;
            }
            bb[tid] = acc;
        }
        return;
    }

    // ----------------------- reduce path -----------------------
    const int rid = blockIdx.x - PREP_BLOCKS;
    const int j = rid & (NN - 1);
    const int b = rid >> 7;

    __shared__ __align__(16) float s_re[8][DD];
    __shared__ __align__(16) float s_rh[8][DD];
    __shared__ float    s_val[NN];
    __shared__ int      s_idx[NN];
    __shared__ unsigned s_ball[4];
    __shared__ float    s_wsum[4];
    __shared__ int      s_cnt;
    __shared__ float    s_deg;

    float a = 0.f;
    if (tid < NN) {
        a = adj[((size_t)b * NN + tid) * NN + j];
        unsigned ball = __ballot_sync(0xffffffffu, a != 0.f);
        float s = a;
        #pragma unroll
        for (int off = 16; off; off >>= 1) s += __shfl_down_sync(0xffffffffu, s, off);
        if (lane == 0) { s_ball[w] = ball; s_wsum[w] = s; }
    }
    __syncthreads();
    if (tid < NN) {
        int base = 0;
        #pragma unroll
        for (int ww = 0; ww < 4; ++ww) if (ww < w) base += __popc(s_ball[ww]);
        const unsigned ball = s_ball[w];
        if (a != 0.f) {
            const int pos = base + __popc(ball & ((1u << lane) - 1u));
            s_idx[pos] = tid;
            s_val[pos] = a;
        }
        if (tid == 0) {
            s_cnt = __popc(s_ball[0]) + __popc(s_ball[1]) + __popc(s_ball[2]) + __popc(s_ball[3]);
            s_deg = s_wsum[0] + s_wsum[1] + s_wsum[2] + s_wsum[3];
        }
    }
    __syncthreads();

    const int   cnt = s_cnt;
    const float deg = s_deg;

    // e[b,i,j,d]: base (i=0) = (b*NN*NN + j)*DD ; stride over i = NN*DD
    const float* __restrict__ eb = e + ((size_t)b * NN * NN + (size_t)j) * DD + lane * 4;
    const float* __restrict__ hb = h + (size_t)b * NN * DD + lane * 4;

    float4 ae = make_float4(0.f, 0.f, 0.f, 0.f);
    float4 ah = make_float4(0.f, 0.f, 0.f, 0.f);
    #pragma unroll 4
    for (int t = w; t < cnt; t += 8) {
        const float aa = s_val[t];
        const int   i  = s_idx[t];
        const float4 ev = *(const float4*)(eb + (size_t)i * (NN * DD));
        const float4 hv = *(const float4*)(hb + (size_t)i * DD);
        ae.x += aa * ev.x; ae.y += aa * ev.y; ae.z += aa * ev.z; ae.w += aa * ev.w;
        ah.x += aa * hv.x; ah.y += aa * hv.y; ah.z += aa * hv.z; ah.w += aa * hv.w;
    }
    *(float4*)&s_re[w][lane * 4] = ae;
    *(float4*)&s_rh[w][lane * 4] = ah;
    __syncthreads();

    if (tid < NN) {
        float se = 0.f, sh = 0.f;
        #pragma unroll
        for (int ww = 0; ww < 8; ++ww) { se += s_re[ww][tid]; sh += s_rh[ww][tid]; }
        const size_t r  = (size_t)b * NN + j;
        const float  hv = h[r * DD + tid];
        xfull[r * 512 + tid]       = sh;        // hhat
        xfull[r * 512 + 128 + tid] = deg * hv;  // deg*h
        xfull[r * 512 + 256 + tid] = se;        // ehat
        xfull[r * 512 + 384 + tid] = hv;        // h
        if (tid == 0) deg_out[r] = deg;
    }
}

// ---------------------------------------------------------------------------
// Final GEMM: C(2048x128) = A(2048x512) @ G(512x128) + deg⊗bb + bu
// BM=32, BN=64, BK=16, 256 threads, TM=2, TN=4, packed f32x2 FMAs.
// grid (2, 64) = 128 blocks.
// ---------------------------------------------------------------------------
#define GBM 32
#define GBN 64
#define GBK 16

__device__ __forceinline__ unsigned long long f2ull(float2 v) {
    unsigned long long u; memcpy(&u, &v, 8); return u;
}
__device__ __forceinline__ float2 ull2f(unsigned long long u) {
    float2 v; memcpy(&v, &u, 8); return v;
}

__global__ void __launch_bounds__(256) gemm_final(
    const float* __restrict__ A,
    const float* __restrict__ G,
    const float* __restrict__ bb,
    const float* __restrict__ bu,
    const float* __restrict__ deg,
    float* __restrict__ C)
{
    __shared__ __align__(16) float2 As2[GBK][GBM + 1];  // duplicated {v,v}
    __shared__ __align__(16) float  Bs[GBK][GBN];

    const int m0 = blockIdx.y * GBM;
    const int n0 = blockIdx.x * GBN;
    const int tid = threadIdx.x;
    const int tx = tid & 15;    // n-group (4 cols)
    const int ty = tid >> 4;    // m-group (2 rows)

    const int am = tid >> 3;          // 0..31
    const int ak = (tid & 7) * 2;     // 0..14
    const int bk = tid >> 4;          // 0..15
    const int bc = (tid & 15) * 4;    // 0..60

    unsigned long long acc[2][2];
    acc[0][0] = acc[0][1] = acc[1][0] = acc[1][1] = 0ull;

    for (int k0 = 0; k0 < 512; k0 += GBK) {
        const float2 av = *(const float2*)(A + (size_t)(m0 + am) * 512 + k0 + ak);
        As2[ak][am]     = make_float2(av.x, av.x);
        As2[ak + 1][am] = make_float2(av.y, av.y);
        *(float4*)&Bs[bk][bc] = *(const float4*)(G + (size_t)(k0 + bk) * 128 + n0 + bc);
        __syncthreads();

        #pragma unroll
        for (int kk = 0; kk < GBK; ++kk) {
            const unsigned long long rm0 = f2ull(As2[kk][ty * 2 + 0]);
            const unsigned long long rm1 = f2ull(As2[kk][ty * 2 + 1]);
            const float4 rn = *(const float4*)&Bs[kk][tx * 4];
            const unsigned long long rnA = f2ull(make_float2(rn.x, rn.y));
            const unsigned long long rnB = f2ull(make_float2(rn.z, rn.w));
            asm("fma.rn.f32x2 %0, %1, %2, %0;" : "+l"(acc[0][0]) : "l"(rm0), "l"(rnA));
            asm("fma.rn.f32x2 %0, %1, %2, %0;" : "+l"(acc[0][1]) : "l"(rm0), "l"(rnB));
            asm("fma.rn.f32x2 %0, %1, %2, %0;" : "+l"(acc[1][0]) : "l"(rm1), "l"(rnA));
            asm("fma.rn.f32x2 %0, %1, %2, %0;" : "+l"(acc[1][1]) : "l"(rm1), "l"(rnB));
        }
        __syncthreads();
    }

    #pragma unroll
    for (int q = 0; q < 2; ++q) {
        const int row = m0 + ty * 2 + q;
        const float dg = deg[row];
        #pragma unroll
        for (int p = 0; p < 2; ++p) {
            const float2 v = ull2f(acc[q][p]);
            const int c0 = n0 + tx * 4 + p * 2;
            C[(size_t)row * 128 + c0]     = v.x + dg * bb[c0]     + bu[c0];
            C[(size_t)row * 128 + c0 + 1] = v.y + dg * bb[c0 + 1] + bu[c0 + 1];
        }
    }
}

// ---------------------------------------------------------------------------
// kernel_launch: inputs: h, adj, e, Wm, bm, Wu, bu ; output (B,N,D) fp32
// ---------------------------------------------------------------------------
extern "C" void kernel_launch(void* const* d_in, const int* in_sizes, int n_in,
                              void* d_out, int out_size)
{
    const float* h   = (const float*)d_in[0];
    const float* adj = (const float*)d_in[1];
    const float* e   = (const float*)d_in[2];
    const float* Wm  = (const float*)d_in[3];
    const float* bm  = (const float*)d_in[4];
    const float* Wu  = (const float*)d_in[5];
    const float* bu  = (const float*)d_in[6];
    float* out = (float*)d_out;

    float* xfull; cudaGetSymbolAddress((void**)&xfull, g_xfull);
    float* G;     cudaGetSymbolAddress((void**)&G,     g_G);
    float* bb;    cudaGetSymbolAddress((void**)&bb,    g_bb);
    float* deg;   cudaGetSymbolAddress((void**)&deg,   g_deg);

    // One fused launch: prep blocks (first, hidden) + reduce blocks
    fused_prep_reduce<<<PREP_BLOCKS + BB * NN, 256>>>(
        h, adj, e, Wm, Wu, bm, xfull, deg, G, bb);

    {
        dim3 grid(128 / GBN, (BB * NN) / GBM);   // (2, 64)
        gemm_final<<<grid, 256>>>(xfull, G, bb, bu, deg, out);
    }
}

// round 7
// speedup vs baseline: 1.5047x; 1.2411x over previous
#include <cuda_runtime.h>
#include <cstdint>
#include <cstring>

#define BB 16
#define NN 128
#define DD 128

#define PREP_BLOCKS 256   // blocks 0..255 of fused kernel do weight-fusion prep

// Split-K GEMM config
#define SK  8     // number of K splits
#define KB  64    // K elements per split (SK*KB = 512)
#define SBM 64    // M tile
#define SBK 16    // inner K tile

// Scratch (device globals — allocations forbidden)
__device__ float g_xfull[BB * NN * 512];     // [hhat | deg*h | ehat | h]  (4 MB)
__device__ float g_G[512 * 128];             // fused weight (256 KB)
__device__ float g_bb[128];                  // bm @ Wu2^T
__device__ float g_deg[BB * NN];
__device__ float g_part[SK * BB * NN * 128]; // split-K partials (8 MB)

__device__ __forceinline__ unsigned long long f2ull(float x, float y) {
    float2 v = make_float2(x, y);
    unsigned long long u; memcpy(&u, &v, 8); return u;
}
__device__ __forceinline__ float2 ull2f(unsigned long long u) {
    float2 v; memcpy(&v, &u, 8); return v;
}

// ---------------------------------------------------------------------------
// Fused kernel: grid = PREP_BLOCKS + B*N blocks, 256 threads.
// blocks [0,256): weight-fusion prep (hidden under reduce's DRAM stream)
// blocks [256, 2304): adj-weighted reduction over i for one (b,j)
// ---------------------------------------------------------------------------
__global__ void __launch_bounds__(256) fused_prep_reduce(
    const float* __restrict__ h,
    const float* __restrict__ adj,
    const float* __restrict__ e,
    const float* __restrict__ Wm,
    const float* __restrict__ Wu,
    const float* __restrict__ bm,
    float* __restrict__ xfull,
    float* __restrict__ deg_out,
    float* __restrict__ G,
    float* __restrict__ bb)
{
    const int tid  = threadIdx.x;
    const int lane = tid & 31;
    const int w    = tid >> 5;

    if (blockIdx.x < PREP_BLOCKS) {
        // ----------------------- prep path -----------------------
        __shared__ float s_wm[2][128];
        const int pid = blockIdx.x;
        const int c0  = pid * 2;
        const int cl  = tid >> 7;       // 0,1
        const int k   = tid & 127;

        {
            const int q  = tid & 127;
            const int cc = c0 + (tid >> 7);
            s_wm[tid >> 7][q] = (cc < 384) ? Wm[(size_t)q * 384 + cc] : 0.f;
        }
        __syncthreads();

        const int c = c0 + cl;
        if (c < 384) {
            const float* __restrict__ wu = Wu + (size_t)k * 256 + 128;
            float acc = 0.f;
            #pragma unroll 4
            for (int q = 0; q < 128; q += 4) {
                const float4 v = *(const float4*)(wu + q);
                acc += s_wm[cl][q]     * v.x;
                acc += s_wm[cl][q + 1] * v.y;
                acc += s_wm[cl][q + 2] * v.z;
                acc += s_wm[cl][q + 3] * v.w;
            }
            G[(size_t)c * 128 + k] = acc;
        } else {
            G[(size_t)c * 128 + k] = Wu[(size_t)k * 256 + (c - 384)];
        }

        if (pid == 0 && tid < 128) {
            const float* __restrict__ wu = Wu + (size_t)tid * 256 + 128;
            float acc = 0.f;
            #pragma unroll 4
            for (int q = 0; q < 128; q += 4) {
                const float4 v  = *(const float4*)(wu + q);
                const float4 bv = *(const float4*)(bm + q);
                acc += bv.x * v.x + bv.y * v.y + bv.z * v.z + bv.w * v.w;
            }
            bb[tid] = acc;
        }
        return;
    }

    // ----------------------- reduce path -----------------------
    const int rid = blockIdx.x - PREP_BLOCKS;
    const int j = rid & (NN - 1);
    const int b = rid >> 7;

    __shared__ __align__(16) float s_re[8][DD];
    __shared__ __align__(16) float s_rh[8][DD];
    __shared__ float    s_val[NN];
    __shared__ int      s_idx[NN];
    __shared__ unsigned s_ball[4];
    __shared__ float    s_wsum[4];
    __shared__ int      s_cnt;
    __shared__ float    s_deg;

    float a = 0.f;
    if (tid < NN) {
        a = adj[((size_t)b * NN + tid) * NN + j];
        unsigned ball = __ballot_sync(0xffffffffu, a != 0.f);
        float s = a;
        #pragma unroll
        for (int off = 16; off; off >>= 1) s += __shfl_down_sync(0xffffffffu, s, off);
        if (lane == 0) { s_ball[w] = ball; s_wsum[w] = s; }
    }
    __syncthreads();
    if (tid < NN) {
        int base = 0;
        #pragma unroll
        for (int ww = 0; ww < 4; ++ww) if (ww < w) base += __popc(s_ball[ww]);
        const unsigned ball = s_ball[w];
        if (a != 0.f) {
            const int pos = base + __popc(ball & ((1u << lane) - 1u));
            s_idx[pos] = tid;
            s_val[pos] = a;
        }
        if (tid == 0) {
            s_cnt = __popc(s_ball[0]) + __popc(s_ball[1]) + __popc(s_ball[2]) + __popc(s_ball[3]);
            s_deg = s_wsum[0] + s_wsum[1] + s_wsum[2] + s_wsum[3];
        }
    }
    __syncthreads();

    const int   cnt = s_cnt;
    const float deg = s_deg;

    const float* __restrict__ eb = e + ((size_t)b * NN * NN + (size_t)j) * DD + lane * 4;
    const float* __restrict__ hb = h + (size_t)b * NN * DD + lane * 4;

    float4 ae = make_float4(0.f, 0.f, 0.f, 0.f);
    float4 ah = make_float4(0.f, 0.f, 0.f, 0.f);
    #pragma unroll 4
    for (int t = w; t < cnt; t += 8) {
        const float aa = s_val[t];
        const int   i  = s_idx[t];
        const float4 ev = *(const float4*)(eb + (size_t)i * (NN * DD));
        const float4 hv = *(const float4*)(hb + (size_t)i * DD);
        ae.x += aa * ev.x; ae.y += aa * ev.y; ae.z += aa * ev.z; ae.w += aa * ev.w;
        ah.x += aa * hv.x; ah.y += aa * hv.y; ah.z += aa * hv.z; ah.w += aa * hv.w;
    }
    *(float4*)&s_re[w][lane * 4] = ae;
    *(float4*)&s_rh[w][lane * 4] = ah;
    __syncthreads();

    if (tid < NN) {
        float se = 0.f, sh = 0.f;
        #pragma unroll
        for (int ww = 0; ww < 8; ++ww) { se += s_re[ww][tid]; sh += s_rh[ww][tid]; }
        const size_t r  = (size_t)b * NN + j;
        const float  hv = h[r * DD + tid];
        xfull[r * 512 + tid]       = sh;        // hhat
        xfull[r * 512 + 128 + tid] = deg * hv;  // deg*h
        xfull[r * 512 + 256 + tid] = se;        // ehat
        xfull[r * 512 + 384 + tid] = hv;        // h
        if (tid == 0) deg_out[r] = deg;
    }
}

// ---------------------------------------------------------------------------
// Split-K GEMM: part[ks] += A[:, ks*64:(ks+1)*64] @ G[ks*64:(ks+1)*64, :]
// Grid (SK, 2048/SBM) = (8, 32) = 256 blocks, 256 threads.
// Thread tile TM=4 x TN=8 via 16 packed f32x2 accumulators.
// ---------------------------------------------------------------------------
__global__ void __launch_bounds__(256) gemm_split(
    const float* __restrict__ A,     // 2048 x 512
    const float* __restrict__ G,     // 512 x 128
    float* __restrict__ part)        // SK x 2048 x 128
{
    __shared__ __align__(16) float As[SBK][76];    // row stride 304B (16B mult)
    __shared__ __align__(16) float Bs[SBK][128];

    const int ks  = blockIdx.x;
    const int m0  = blockIdx.y * SBM;
    const int kb  = ks * KB;
    const int tid = threadIdx.x;
    const int tx  = tid & 15;     // n-group: 8 cols
    const int ty  = tid >> 4;     // m-group: 4 rows

    const int am = tid >> 2;          // 0..63
    const int ak = (tid & 3) * 4;     // 0,4,8,12
    const int bk = tid >> 4;          // 0..15
    const int bc = (tid & 15) * 8;    // 0..120

    unsigned long long acc[4][4];
    #pragma unroll
    for (int i = 0; i < 4; ++i)
        #pragma unroll
        for (int jj = 0; jj < 4; ++jj) acc[i][jj] = 0ull;

    for (int t = 0; t < KB; t += SBK) {
        const float4 av = *(const float4*)(A + (size_t)(m0 + am) * 512 + kb + t + ak);
        As[ak + 0][am] = av.x; As[ak + 1][am] = av.y;
        As[ak + 2][am] = av.z; As[ak + 3][am] = av.w;
        const float* gr = G + (size_t)(kb + t + bk) * 128 + bc;
        *(float4*)&Bs[bk][bc]     = *(const float4*)(gr);
        *(float4*)&Bs[bk][bc + 4] = *(const float4*)(gr + 4);
        __syncthreads();

        #pragma unroll
        for (int kk = 0; kk < SBK; ++kk) {
            const float4 a  = *(const float4*)&As[kk][ty * 4];
            const float4 b0 = *(const float4*)&Bs[kk][tx * 8];
            const float4 b1 = *(const float4*)&Bs[kk][tx * 8 + 4];
            unsigned long long aa[4], bbv[4];
            aa[0] = f2ull(a.x, a.x); aa[1] = f2ull(a.y, a.y);
            aa[2] = f2ull(a.z, a.z); aa[3] = f2ull(a.w, a.w);
            bbv[0] = f2ull(b0.x, b0.y); bbv[1] = f2ull(b0.z, b0.w);
            bbv[2] = f2ull(b1.x, b1.y); bbv[3] = f2ull(b1.z, b1.w);
            #pragma unroll
            for (int i = 0; i < 4; ++i)
                #pragma unroll
                for (int jj = 0; jj < 4; ++jj)
                    asm("fma.rn.f32x2 %0, %1, %2, %0;"
                        : "+l"(acc[i][jj]) : "l"(aa[i]), "l"(bbv[jj]));
        }
        __syncthreads();
    }

    float* p = part + (size_t)ks * (BB * NN * 128);
    #pragma unroll
    for (int i = 0; i < 4; ++i) {
        const int row = m0 + ty * 4 + i;
        const float2 v0 = ull2f(acc[i][0]);
        const float2 v1 = ull2f(acc[i][1]);
        const float2 v2 = ull2f(acc[i][2]);
        const float2 v3 = ull2f(acc[i][3]);
        float4 o0 = make_float4(v0.x, v0.y, v1.x, v1.y);
        float4 o1 = make_float4(v2.x, v2.y, v3.x, v3.y);
        *(float4*)(p + (size_t)row * 128 + tx * 8)     = o0;
        *(float4*)(p + (size_t)row * 128 + tx * 8 + 4) = o1;
    }
}

// ---------------------------------------------------------------------------
// finish: C[row,col] = sum_ks part[ks,row,col] + deg[row]*bb[col] + bu[col]
// 65536 float4-threads: grid 512 x 128.
// ---------------------------------------------------------------------------
__global__ void __launch_bounds__(128) finish_kernel(
    const float* __restrict__ part,
    const float* __restrict__ bb,
    const float* __restrict__ bu,
    const float* __restrict__ deg,
    float* __restrict__ C)
{
    const int t   = blockIdx.x * 128 + threadIdx.x;  // 0..65535
    const int row = t >> 5;
    const int c4  = (t & 31) * 4;
    const size_t off = (size_t)row * 128 + c4;

    float4 s = make_float4(0.f, 0.f, 0.f, 0.f);
    #pragma unroll
    for (int ks = 0; ks < SK; ++ks) {
        const float4 v = *(const float4*)(part + (size_t)ks * (BB * NN * 128) + off);
        s.x += v.x; s.y += v.y; s.z += v.z; s.w += v.w;
    }
    const float dg = __ldg(deg + row);
    const float4 bbv = *(const float4*)(bb + c4);
    const float4 buv = *(const float4*)(bu + c4);
    s.x += dg * bbv.x + buv.x;
    s.y += dg * bbv.y + buv.y;
    s.z += dg * bbv.z + buv.z;
    s.w += dg * bbv.w + buv.w;
    *(float4*)(C + off) = s;
}

// ---------------------------------------------------------------------------
// kernel_launch: inputs: h, adj, e, Wm, bm, Wu, bu ; output (B,N,D) fp32
// ---------------------------------------------------------------------------
extern "C" void kernel_launch(void* const* d_in, const int* in_sizes, int n_in,
                              void* d_out, int out_size)
{
    const float* h   = (const float*)d_in[0];
    const float* adj = (const float*)d_in[1];
    const float* e   = (const float*)d_in[2];
    const float* Wm  = (const float*)d_in[3];
    const float* bm  = (const float*)d_in[4];
    const float* Wu  = (const float*)d_in[5];
    const float* bu  = (const float*)d_in[6];
    float* out = (float*)d_out;

    float* xfull; cudaGetSymbolAddress((void**)&xfull, g_xfull);
    float* G;     cudaGetSymbolAddress((void**)&G,     g_G);
    float* bb;    cudaGetSymbolAddress((void**)&bb,    g_bb);
    float* deg;   cudaGetSymbolAddress((void**)&deg,   g_deg);
    float* part;  cudaGetSymbolAddress((void**)&part,  g_part);

    fused_prep_reduce<<<PREP_BLOCKS + BB * NN, 256>>>(
        h, adj, e, Wm, Wu, bm, xfull, deg, G, bb);

    {
        dim3 grid(SK, (BB * NN) / SBM);   // (8, 32)
        gemm_split<<<grid, 256>>>(xfull, G, part);
    }
    finish_kernel<<<512, 128>>>(part, bb, bu, deg, out);
}